// round 1
// baseline (speedup 1.0000x reference)
#include <cuda_runtime.h>

namespace {
constexpr int NND  = 21;    // hand nodes
constexpr int FIN  = 256;
constexpr int DM   = 128;
constexpr int FOUT = 512;
constexpr int ODIM = 3;
constexpr int X3LD = 132;   // padded smem row stride for x3 chunk (bank spread)

// acc[m] += sum_k sin[m][k] * W[k][o-column], K-vectorized by 4, W prefetch depth 1.
template<int K>
__device__ __forceinline__ void dot21(const float* __restrict__ sin,
                                      const float* __restrict__ Wp, int ldw,
                                      float acc[NND]) {
    #pragma unroll
    for (int m = 0; m < NND; ++m) acc[m] = 0.f;
    float w0 = Wp[0], w1 = Wp[ldw], w2 = Wp[2*ldw], w3 = Wp[3*ldw];
    #pragma unroll 1
    for (int kq = 0; kq < K/4; ++kq) {
        float n0 = 0.f, n1 = 0.f, n2 = 0.f, n3 = 0.f;
        if (kq + 1 < K/4) {   // prefetch next W quad while FFMAs run
            const float* p = Wp + (size_t)(kq + 1) * 4 * ldw;
            n0 = p[0]; n1 = p[ldw]; n2 = p[2*ldw]; n3 = p[3*ldw];
        }
        #pragma unroll
        for (int m = 0; m < NND; ++m) {
            float4 xv = *reinterpret_cast<const float4*>(sin + m*K + kq*4);
            acc[m] = fmaf(xv.x, w0, acc[m]);
            acc[m] = fmaf(xv.y, w1, acc[m]);
            acc[m] = fmaf(xv.z, w2, acc[m]);
            acc[m] = fmaf(xv.w, w3, acc[m]);
        }
        w0 = n0; w1 = n1; w2 = n2; w3 = n3;
    }
}
} // namespace

__global__ void __launch_bounds__(128, 4)
handnet_fused(const float* __restrict__ x,
              const float* __restrict__ A1, const float* __restrict__ A2,
              const float* __restrict__ A3,
              const float* __restrict__ W1, const float* __restrict__ b1,
              const float* __restrict__ W2, const float* __restrict__ b2,
              const float* __restrict__ W3, const float* __restrict__ b3,
              const float* __restrict__ fcW, const float* __restrict__ fcb,
              float* __restrict__ x3g, float* __restrict__ outg)
{
    __shared__ float xs [NND*FIN];    // 21504 B; reused as x3 chunk [21][X3LD]
    __shared__ float x1s[NND*DM];     // 10752 B
    __shared__ float x2s[NND*DM];     // 10752 B
    __shared__ float As [3*NND*NND];  //  5292 B
    __shared__ float outs[NND*ODIM];  //   252 B   (total 48552 B, static <48K)

    const int tid = threadIdx.x;
    const int b   = blockIdx.x;
    const int o   = tid;              // output-feature lane 0..127

    // -------- stage inputs --------
    {
        const float4* xg  = reinterpret_cast<const float4*>(x + (size_t)b * NND * FIN);
        float4*       xs4 = reinterpret_cast<float4*>(xs);
        for (int i = tid; i < NND*FIN/4; i += 128) xs4[i] = xg[i];
        for (int i = tid; i < NND*NND;   i += 128) {
            As[i]             = A1[i];
            As[NND*NND + i]   = A2[i];
            As[2*NND*NND + i] = A3[i];
        }
        if (tid < NND*ODIM) outs[tid] = 0.f;
    }
    __syncthreads();

    float acc[NND];

    // -------- layer 1: relu(A1 @ (x @ W1) + b1) --------
    dot21<FIN>(xs, W1 + o, DM, acc);
    {
        const float bias = __ldg(b1 + o);
        const float* Ar  = As;
        #pragma unroll
        for (int n = 0; n < NND; ++n) {
            float s = bias;
            #pragma unroll
            for (int m = 0; m < NND; ++m) s = fmaf(Ar[n*NND + m], acc[m], s);
            x1s[n*DM + o] = fmaxf(s, 0.f);
        }
    }
    __syncthreads();

    // -------- layer 2: relu(A2 @ (x1 @ W2) + b2) --------
    dot21<DM>(x1s, W2 + o, DM, acc);
    {
        const float bias = __ldg(b2 + o);
        const float* Ar  = As + NND*NND;
        #pragma unroll
        for (int n = 0; n < NND; ++n) {
            float s = bias;
            #pragma unroll
            for (int m = 0; m < NND; ++m) s = fmaf(Ar[n*NND + m], acc[m], s);
            x2s[n*DM + o] = fmaxf(s, 0.f);
        }
    }
    __syncthreads();

    // -------- layer 3 (4 feature chunks of 128) + fused FC head --------
    float* x3s = xs;  // xs dead after layer 1; reuse as staging for FC
    #pragma unroll 1
    for (int c = 0; c < 4; ++c) {
        dot21<DM>(x2s, W3 + c*DM + o, FOUT, acc);
        const float bias = __ldg(b3 + c*DM + o);
        const float* Ar  = As + 2*NND*NND;
        #pragma unroll
        for (int n = 0; n < NND; ++n) {
            float s = bias;
            #pragma unroll
            for (int m = 0; m < NND; ++m) s = fmaf(Ar[n*NND + m], acc[m], s);
            s = fmaxf(s, 0.f);
            x3s[n*X3LD + o] = s;
            x3g[((size_t)b*NND + n)*FOUT + c*DM + o] = s;
        }
        __syncthreads();
        // FC partial: 63 threads own (node m, out j); sum this chunk's 128 feats
        if (tid < NND*ODIM) {
            const int m = tid / ODIM, j = tid % ODIM;
            const float* w  = fcW + (c*DM)*ODIM + j;
            const float* xr = x3s + m*X3LD;
            float s = 0.f;
            #pragma unroll 1
            for (int fq = 0; fq < DM/4; ++fq) {
                float4 xv = *reinterpret_cast<const float4*>(xr + 4*fq);
                s = fmaf(xv.x, __ldg(w + (4*fq+0)*ODIM), s);
                s = fmaf(xv.y, __ldg(w + (4*fq+1)*ODIM), s);
                s = fmaf(xv.z, __ldg(w + (4*fq+2)*ODIM), s);
                s = fmaf(xv.w, __ldg(w + (4*fq+3)*ODIM), s);
            }
            outs[tid] += s;
        }
        __syncthreads();  // protect x3s before next chunk overwrites it
    }

    // -------- final out = FC + fcb --------
    if (tid < NND*ODIM) {
        const int m = tid / ODIM, j = tid % ODIM;
        outg[((size_t)b*NND + m)*ODIM + j] = outs[tid] + __ldg(fcb + j);
    }
}

extern "C" void kernel_launch(void* const* d_in, const int* in_sizes, int n_in,
                              void* d_out, int out_size) {
    const float* x   = (const float*)d_in[0];
    const float* A1  = (const float*)d_in[1];
    const float* A2  = (const float*)d_in[2];
    const float* A3  = (const float*)d_in[3];
    const float* W1  = (const float*)d_in[4];
    const float* b1  = (const float*)d_in[5];
    const float* W2  = (const float*)d_in[6];
    const float* b2  = (const float*)d_in[7];
    const float* W3  = (const float*)d_in[8];
    const float* b3  = (const float*)d_in[9];
    const float* fcW = (const float*)d_in[10];
    const float* fcb = (const float*)d_in[11];

    const int Btot = in_sizes[0] / (21 * 256);   // 8192
    float* x3g  = (float*)d_out;
    float* outg = x3g + (size_t)Btot * 21 * 512;

    handnet_fused<<<Btot, 128>>>(x, A1, A2, A3, W1, b1, W2, b2, W3, b3,
                                 fcW, fcb, x3g, outg);
}

// round 4
// speedup vs baseline: 1.4928x; 1.4928x over previous
#include <cuda_runtime.h>
#include <cuda_bf16.h>
#include <cstdint>

// ============================================================
// Portable-PTX (base sm_103) tensor path: ldmatrix + mma.sync bf16
// ============================================================
__device__ __forceinline__ uint32_t smem_u32(const void* p) {
    uint32_t a;
    asm("{ .reg .u64 t; cvta.to.shared.u64 t, %1; cvt.u32.u64 %0, t; }" : "=r"(a) : "l"(p));
    return a;
}
#define LDSM_X4(a0,a1,a2,a3,addr) \
    asm volatile("ldmatrix.sync.aligned.m8n8.x4.shared.b16 {%0,%1,%2,%3}, [%4];" \
        : "=r"(a0), "=r"(a1), "=r"(a2), "=r"(a3) : "r"(addr))
#define MMA_BF16(c, a, b0, b1) \
    asm volatile("mma.sync.aligned.m16n8k16.row.col.f32.bf16.bf16.f32 " \
        "{%0,%1,%2,%3}, {%4,%5,%6,%7}, {%8,%9}, {%0,%1,%2,%3};" \
        : "+f"((c)[0]), "+f"((c)[1]), "+f"((c)[2]), "+f"((c)[3]) \
        : "r"((a)[0]), "r"((a)[1]), "r"((a)[2]), "r"((a)[3]), "r"(b0), "r"(b1))

namespace {
constexpr int LDX = 136;   // bf16 row stride (272 B = 17*16B -> LDSM conflict-free)
constexpr int LDD = 129;   // f32 col-major staging stride (odd -> conflict-free)
// dynamic smem offsets
constexpr int OFF_XH   = 0;              // [128][136] bf16 = 34816
constexpr int OFF_XL   = 34816;          // [128][136] bf16 = 34816
constexpr int OFF_DST  = 69632;          // [64][129] f32   = 33024
constexpr int OFF_AW   = 102656;         // [3][21][24] f32 = 6048
constexpr int OFF_AI   = 108704;         // [3][21][24] u8  = 1512
constexpr int OFF_ACNT = 110216;         // [64] i32        = 256
constexpr int OFF_OAC  = 110472;         // [384] f32       = 1536
constexpr int OFF_ROWN = 112008;         // rown[128] + gb[128] u8
constexpr int SMEM_SZ  = 112384;
// B-fragment segment bases (in fragset units)
constexpr int SEG_W1 = 0;      // 16 ks * 16 nt * 2 parts = 512
constexpr int SEG_W2 = 512;    //  8 ks * 16 nt * 2       = 256
constexpr int SEG_W3 = 768;    //  8 ks * 64 nt * 2       = 1024
constexpr int NFRAG  = 1792;
} // namespace

// Per-lane precomputed B fragments (bf16x2 pairs), hi/lo parts. L2-resident.
__device__ uint2 gWB[NFRAG][32];

__device__ __forceinline__ uint32_t pack_bf2(float x, float y) {
    __nv_bfloat162 h = __floats2bfloat162_rn(x, y);
    return *reinterpret_cast<uint32_t*>(&h);
}

// Expand W into mma B-fragment layout: fragset id = seg + (ks*NT + nt)*2 + part.
// b0 holds B[k0+(l&3)*2 +{0,1}][n0+l/4], b1 the +8 k rows. part0=hi, part1=lo.
__global__ void prep_frags(const float* __restrict__ W1,
                           const float* __restrict__ W2,
                           const float* __restrict__ W3) {
    const int id = blockIdx.x, l = threadIdx.x;
    const float* W; int ld, r;
    if (id < 512)      { W = W1; ld = 128; r = id; }
    else if (id < 768) { W = W2; ld = 128; r = id - 512; }
    else               { W = W3; ld = 512; r = id - 768; }
    const int part = r & 1; r >>= 1;
    const int NT = (id < 768) ? 16 : 64;
    const int nt = r % NT, ks = r / NT;
    const int n  = nt * 8 + (l >> 2);
    const int k0 = ks * 16 + (l & 3) * 2;

    float v[4];
    #pragma unroll
    for (int i = 0; i < 4; ++i) {
        int k = k0 + (i >> 1) * 8 + (i & 1);
        float w = W[(size_t)k * ld + n];
        float hi = __bfloat162float(__float2bfloat16(w));
        v[i] = part ? (w - hi) : hi;
    }
    gWB[id][l] = make_uint2(pack_bf2(v[0], v[1]), pack_bf2(v[2], v[3]));
}

// 3-pass (AhiBhi, AhiBlo, AloBhi) sweep over nks ksteps of the current X chunk.
__device__ __forceinline__ void sweep3(float C[2][8][4], uint32_t xh, uint32_t xl,
                                       int segbase, int NTseg, int ks0, int nks,
                                       int ntw, int arow, int kadd, int lane) {
    #pragma unroll 1
    for (int p = 0; p < 3; ++p) {
        const uint32_t xb = (p == 2) ? xl : xh;
        const int pb = (p == 1) ? 1 : 0;
        #pragma unroll 1
        for (int ks = 0; ks < nks; ++ks) {
            uint2 b[8];
            const uint2* bp = &gWB[segbase + ((ks0 + ks) * NTseg + ntw) * 2 + pb][lane];
            #pragma unroll
            for (int j = 0; j < 8; ++j) b[j] = __ldg(bp + j * 64);
            uint32_t a[2][4];
            #pragma unroll
            for (int mt = 0; mt < 2; ++mt) {
                uint32_t ad = xb + (uint32_t)(((arow + mt * 16) * LDX + ks * 16 + kadd) * 2);
                LDSM_X4(a[mt][0], a[mt][1], a[mt][2], a[mt][3], ad);
            }
            #pragma unroll
            for (int mt = 0; mt < 2; ++mt)
                #pragma unroll
                for (int j = 0; j < 8; ++j)
                    MMA_BF16(C[mt][j], a[mt], b[j].x, b[j].y);
        }
    }
}

__global__ void __launch_bounds__(256, 2)
handnet_mma(const float* __restrict__ x,
            const float* __restrict__ A1, const float* __restrict__ A2,
            const float* __restrict__ A3,
            const float* __restrict__ b1, const float* __restrict__ b2,
            const float* __restrict__ b3,
            const float* __restrict__ fcW, const float* __restrict__ fcb,
            float* __restrict__ x3g, float* __restrict__ outg, int Btot)
{
    extern __shared__ unsigned char sm[];
    __nv_bfloat16* XH = (__nv_bfloat16*)(sm + OFF_XH);
    __nv_bfloat16* XL = (__nv_bfloat16*)(sm + OFF_XL);
    float*   Dst  = (float*)(sm + OFF_DST);
    float*   Aw   = (float*)(sm + OFF_AW);
    uint8_t* Ai   = sm + OFF_AI;
    int*     Acnt = (int*)(sm + OFF_ACNT);
    float*   Oac  = (float*)(sm + OFF_OAC);
    uint8_t* rown = sm + OFF_ROWN;
    uint8_t* gbas = sm + OFF_ROWN + 128;

    const int tid = threadIdx.x, lane = tid & 31, wid = tid >> 5;
    const int mg = wid >> 1, ng = wid & 1;           // 4 m-groups x 2 n-groups
    const int m0base = mg * 32;
    const int arow = m0base + (lane & 7) + ((lane >> 3) & 1) * 8;
    const int kadd = ((lane >> 4) & 1) * 8;
    const uint32_t xh = smem_u32(XH), xl = smem_u32(XL);

    const int b0row = blockIdx.x * 126;
    const int rows_valid = min(126, Btot * 21 - b0row);

    // ---- setup: LUTs, sparse A lists, accumاست zero ----
    if (tid < 128) { rown[tid] = (uint8_t)(tid % 21); gbas[tid] = (uint8_t)(tid - tid % 21); }
    if (tid < 63) {
        int L = tid / 21, n = tid % 21;
        const float* A = (L == 0) ? A1 : ((L == 1) ? A2 : A3);
        int c = 0;
        for (int m = 0; m < 21; ++m) {
            float v = __ldg(A + n * 21 + m);
            if (v != 0.f) { Aw[(L * 21 + n) * 24 + c] = v; Ai[(L * 21 + n) * 24 + c] = (uint8_t)m; ++c; }
        }
        Acnt[L * 21 + n] = c;
    }
    for (int i = tid; i < 384; i += 256) Oac[i] = 0.f;

    float C[2][8][4];
    #define ZERO_C() { _Pragma("unroll") for (int mt=0;mt<2;++mt) _Pragma("unroll") \
        for (int j=0;j<8;++j) { C[mt][j][0]=0.f;C[mt][j][1]=0.f;C[mt][j][2]=0.f;C[mt][j][3]=0.f; } }

    // ---- stage one 128-col chunk of input x as hi/lo bf16 ----
    #define LOAD_X_CHUNK(kc) { __syncthreads(); \
        for (int i = tid; i < 4096; i += 256) { \
            int r = i >> 5, q = i & 31; \
            float4 v = (r < rows_valid) \
                ? __ldg((const float4*)(x + (size_t)(b0row + r) * 256 + (kc) * 128) + q) \
                : make_float4(0.f, 0.f, 0.f, 0.f); \
            float h0 = __bfloat162float(__float2bfloat16(v.x)); \
            float h1 = __bfloat162float(__float2bfloat16(v.y)); \
            float h2 = __bfloat162float(__float2bfloat16(v.z)); \
            float h3 = __bfloat162float(__float2bfloat16(v.w)); \
            uint2* dh = (uint2*)(XH + r * LDX + q * 4); \
            uint2* dl = (uint2*)(XL + r * LDX + q * 4); \
            *dh = make_uint2(pack_bf2(h0, h1), pack_bf2(h2, h3)); \
            *dl = make_uint2(pack_bf2(v.x - h0, v.y - h1), pack_bf2(v.z - h2, v.w - h3)); \
        } __syncthreads(); }

    // store this warp's C tile into Dst (col-major, 64-col half owned by ng)
    #define STORE_C_HALF() { _Pragma("unroll") for (int mt=0;mt<2;++mt) \
        _Pragma("unroll") for (int j=0;j<8;++j) { \
            int r0 = m0base + mt*16 + (lane>>2); \
            int lc = j*8 + (lane&3)*2; \
            Dst[lc*LDD + r0]       = C[mt][j][0]; \
            Dst[(lc+1)*LDD + r0]   = C[mt][j][1]; \
            Dst[lc*LDD + r0+8]     = C[mt][j][2]; \
            Dst[(lc+1)*LDD + r0+8] = C[mt][j][3]; } }

    // ================= Layer 1: K=256 (2 chunks), N=128 =================
    ZERO_C();
    LOAD_X_CHUNK(0);
    sweep3(C, xh, xl, SEG_W1, 16, 0, 8, ng * 8, arow, kadd, lane);
    LOAD_X_CHUNK(1);
    sweep3(C, xh, xl, SEG_W1, 16, 8, 8, ng * 8, arow, kadd, lane);

    // epilogue for layers 1/2: A-mix + bias + relu -> new hi/lo activations in XH/XL
    #define EPI12(Lyr, bias) { \
        _Pragma("unroll 1") for (int cc = 0; cc < 2; ++cc) { \
            __syncthreads(); \
            if (ng == cc) STORE_C_HALF(); \
            __syncthreads(); \
            int c = tid & 63, rg = tid >> 6, cglob = cc * 64 + c; \
            float bi = __ldg((bias) + cglob); \
            const float* dcol = Dst + c * LDD; \
            _Pragma("unroll 1") for (int rr = 0; rr < 32; ++rr) { \
                int r = rg * 32 + rr; \
                if (r >= rows_valid) continue; \
                int n = rown[r], gb = gbas[r]; \
                int base = ((Lyr) * 21 + n) * 24, cnt = Acnt[(Lyr) * 21 + n]; \
                float s = bi; \
                for (int e = 0; e < cnt; ++e) \
                    s = fmaf(Aw[base + e], dcol[gb + Ai[base + e]], s); \
                s = fmaxf(s, 0.f); \
                float hi = __bfloat162float(__float2bfloat16(s)); \
                XH[r * LDX + cglob] = __float2bfloat16(hi); \
                XL[r * LDX + cglob] = __float2bfloat16(s - hi); \
            } \
        } __syncthreads(); }

    EPI12(0, b1);

    // ================= Layer 2: K=128, N=128 =================
    ZERO_C();
    sweep3(C, xh, xl, SEG_W2, 16, 0, 8, ng * 8, arow, kadd, lane);
    EPI12(1, b2);

    // ================= Layer 3: K=128, N=512 (4 n-chunks) + fused FC ======
    #pragma unroll 1
    for (int nc = 0; nc < 4; ++nc) {
        ZERO_C();
        sweep3(C, xh, xl, SEG_W3, 64, 0, 8, nc * 16 + ng * 8, arow, kadd, lane);
        #pragma unroll 1
        for (int cc = 0; cc < 2; ++cc) {
            __syncthreads();
            if (ng == cc) STORE_C_HALF();
            __syncthreads();
            const int c = tid & 63, rg = tid >> 6;
            const int cglob = nc * 128 + cc * 64 + c;
            const float bi = __ldg(b3 + cglob);
            const float* dcol = Dst + c * LDD;
            float sreg[32];
            #pragma unroll 1
            for (int rr = 0; rr < 32; ++rr) {
                int r = rg * 32 + rr;
                float s = 0.f;
                if (r < rows_valid) {
                    int n = rown[r], gb = gbas[r];
                    int base = (2 * 21 + n) * 24, cnt = Acnt[2 * 21 + n];
                    s = bi;
                    for (int e = 0; e < cnt; ++e)
                        s = fmaf(Aw[base + e], dcol[gb + Ai[base + e]], s);
                    s = fmaxf(s, 0.f);
                    x3g[(size_t)(b0row + r) * 512 + cglob] = s;
                }
                sreg[rr] = s;
            }
            __syncthreads();
            #pragma unroll
            for (int rr = 0; rr < 32; ++rr)
                Dst[c * LDD + rg * 32 + rr] = sreg[rr];
            __syncthreads();
            for (int w = tid; w < 378; w += 256) {
                int r = w / 3, j = w - 3 * r;
                if (r < rows_valid) {
                    float s = 0.f;
                    const int fbase = nc * 128 + cc * 64;
                    #pragma unroll 4
                    for (int c2 = 0; c2 < 64; ++c2)
                        s = fmaf(Dst[c2 * LDD + r],
                                 __ldg(fcW + (size_t)(fbase + c2) * 3 + j), s);
                    Oac[w] += s;
                }
            }
            __syncthreads();
        }
    }

    // ---- final out = FC + fcb ----
    for (int w = tid; w < 378; w += 256) {
        int r = w / 3, j = w - 3 * r;
        if (r < rows_valid)
            outg[(size_t)(b0row + r) * 3 + j] = Oac[w] + __ldg(fcb + j);
    }
    #undef ZERO_C
    #undef LOAD_X_CHUNK
    #undef STORE_C_HALF
    #undef EPI12
}

extern "C" void kernel_launch(void* const* d_in, const int* in_sizes, int n_in,
                              void* d_out, int out_size) {
    const float* x   = (const float*)d_in[0];
    const float* A1  = (const float*)d_in[1];
    const float* A2  = (const float*)d_in[2];
    const float* A3  = (const float*)d_in[3];
    const float* W1  = (const float*)d_in[4];
    const float* b1  = (const float*)d_in[5];
    const float* W2  = (const float*)d_in[6];
    const float* b2  = (const float*)d_in[7];
    const float* W3  = (const float*)d_in[8];
    const float* b3  = (const float*)d_in[9];
    const float* fcW = (const float*)d_in[10];
    const float* fcb = (const float*)d_in[11];

    const int Btot = in_sizes[0] / (21 * 256);
    float* x3g  = (float*)d_out;
    float* outg = x3g + (size_t)Btot * 21 * 512;

    static int attr_done = 0;
    if (!attr_done) {
        cudaFuncSetAttribute(handnet_mma, cudaFuncAttributeMaxDynamicSharedMemorySize, SMEM_SZ);
        attr_done = 1;
    }

    prep_frags<<<NFRAG, 32>>>(W1, W2, W3);
    const int nCTA = (Btot * 21 + 125) / 126;
    handnet_mma<<<nCTA, 256, SMEM_SZ>>>(x, A1, A2, A3, b1, b2, b3, fcW, fcb,
                                        x3g, outg, Btot);
}

// round 5
// speedup vs baseline: 1.9195x; 1.2859x over previous
#include <cuda_runtime.h>
#include <cuda_bf16.h>
#include <cstdint>

// ============================================================
// Portable-PTX (base sm_103) tensor path: ldmatrix + mma.sync bf16
// ============================================================
__device__ __forceinline__ uint32_t smem_u32(const void* p) {
    uint32_t a;
    asm("{ .reg .u64 t; cvta.to.shared.u64 t, %1; cvt.u32.u64 %0, t; }" : "=r"(a) : "l"(p));
    return a;
}
#define LDSM_X4(a0,a1,a2,a3,addr) \
    asm volatile("ldmatrix.sync.aligned.m8n8.x4.shared.b16 {%0,%1,%2,%3}, [%4];" \
        : "=r"(a0), "=r"(a1), "=r"(a2), "=r"(a3) : "r"(addr))
#define MMA_BF16(c, a, b0, b1) \
    asm volatile("mma.sync.aligned.m16n8k16.row.col.f32.bf16.bf16.f32 " \
        "{%0,%1,%2,%3}, {%4,%5,%6,%7}, {%8,%9}, {%0,%1,%2,%3};" \
        : "+f"((c)[0]), "+f"((c)[1]), "+f"((c)[2]), "+f"((c)[3]) \
        : "r"((a)[0]), "r"((a)[1]), "r"((a)[2]), "r"((a)[3]), "r"(b0), "r"(b1))

namespace {
constexpr int LDX = 136;        // bf16 row stride (272 B = 17*16B -> LDSM conflict-free)
constexpr int ANN = 12;         // max nnz per A row (hand graph max degree+self = 6)
// dynamic smem offsets
constexpr int OFF_XH   = 0;              // [128][136] bf16 = 34816
constexpr int OFF_XL   = 34816;          // [128][136] bf16 = 34816
constexpr int OFF_AW   = 69632;          // [3][21][12] f32 = 3024
constexpr int OFF_AI   = 72656;          // [3][21][12] u8  = 756 (+pad)
constexpr int OFF_ACNT = 73424;          // [64] i32 = 256
constexpr int OFF_OAC  = 73680;          // [384] f32 = 1536
constexpr int OFF_ROWN = 75216;          // rown[128] + gbas[128] u8
constexpr int SMEM_SZ  = 75520;
// B-fragment segment bases (in fragset units)
constexpr int SEG_W1 = 0;      // 16 ks * 16 nt * 2 parts = 512
constexpr int SEG_W2 = 512;    //  8 ks * 16 nt * 2       = 256
constexpr int SEG_W3 = 768;    //  8 ks * 64 nt * 2       = 1024
constexpr int NFRAG  = 1792;
} // namespace

// Per-lane precomputed B fragments (bf16x2 pairs), hi/lo parts. L2-resident.
__device__ uint2 gWB[NFRAG][32];

__device__ __forceinline__ uint32_t pack_bf2(float x, float y) {
    __nv_bfloat162 h = __floats2bfloat162_rn(x, y);
    return *reinterpret_cast<uint32_t*>(&h);
}

// Expand W into mma B-fragment layout: fragset id = seg + (ks*NT + nt)*2 + part.
__global__ void prep_frags(const float* __restrict__ W1,
                           const float* __restrict__ W2,
                           const float* __restrict__ W3) {
    const int id = blockIdx.x, l = threadIdx.x;
    const float* W; int ld, r;
    if (id < 512)      { W = W1; ld = 128; r = id; }
    else if (id < 768) { W = W2; ld = 128; r = id - 512; }
    else               { W = W3; ld = 512; r = id - 768; }
    const int part = r & 1; r >>= 1;
    const int NT = (id < 768) ? 16 : 64;
    const int nt = r % NT, ks = r / NT;
    const int n  = nt * 8 + (l >> 2);
    const int k0 = ks * 16 + (l & 3) * 2;

    float v[4];
    #pragma unroll
    for (int i = 0; i < 4; ++i) {
        int k = k0 + (i >> 1) * 8 + (i & 1);
        float w = W[(size_t)k * ld + n];
        float hi = __bfloat162float(__float2bfloat16(w));
        v[i] = part ? (w - hi) : hi;
    }
    gWB[id][l] = make_uint2(pack_bf2(v[0], v[1]), pack_bf2(v[2], v[3]));
}

__global__ void __launch_bounds__(256, 2)
handnet_mma(const float* __restrict__ x,
            const float* __restrict__ A1, const float* __restrict__ A2,
            const float* __restrict__ A3,
            const float* __restrict__ b1, const float* __restrict__ b2,
            const float* __restrict__ b3,
            const float* __restrict__ fcW, const float* __restrict__ fcb,
            float* __restrict__ x3g, float* __restrict__ outg, int Btot)
{
    extern __shared__ unsigned char sm[];
    __nv_bfloat16* XH = (__nv_bfloat16*)(sm + OFF_XH);
    __nv_bfloat16* XL = (__nv_bfloat16*)(sm + OFF_XL);
    float*   Aw   = (float*)(sm + OFF_AW);
    uint8_t* Ai   = sm + OFF_AI;
    int*     Acnt = (int*)(sm + OFF_ACNT);
    float*   Oac  = (float*)(sm + OFF_OAC);
    uint8_t* rown = sm + OFF_ROWN;

    const int tid = threadIdx.x, lane = tid & 31, wid = tid >> 5;
    const int mg = wid >> 1, ng = wid & 1;           // 4 m-groups x 2 n-groups
    const int m0base = mg * 32;
    const int arow = m0base + (lane & 7) + ((lane >> 3) & 1) * 8;
    const int kadd = ((lane >> 4) & 1) * 8;
    const uint32_t xh = smem_u32(XH), xl = smem_u32(XL);

    const int b0row = blockIdx.x * 126;
    const int rows_valid = min(126, Btot * 21 - b0row);

    // ---- setup: LUTs, sparse A lists, Oac zero ----
    if (tid < 128) rown[tid] = (uint8_t)(tid % 21);
    if (tid < 63) {
        int L = tid / 21, n = tid % 21;
        const float* A = (L == 0) ? A1 : ((L == 1) ? A2 : A3);
        int c = 0;
        for (int m = 0; m < 21 && c < ANN; ++m) {
            float v = __ldg(A + n * 21 + m);
            if (v != 0.f) { Aw[(L*21+n)*ANN + c] = v; Ai[(L*21+n)*ANN + c] = (uint8_t)m; ++c; }
        }
        Acnt[L * 21 + n] = c;
    }
    for (int i = tid; i < 384; i += 256) Oac[i] = 0.f;
    __syncthreads();

    float C[2][8][4];
    #define ZERO_C() { _Pragma("unroll") for (int mt=0;mt<2;++mt) _Pragma("unroll") \
        for (int j=0;j<8;++j) { C[mt][j][0]=0.f;C[mt][j][1]=0.f;C[mt][j][2]=0.f;C[mt][j][3]=0.f; } }

    // ---- fused 3-pass GEMM sweep over nks k-steps (B hi+lo loaded once) ----
    auto sweepK = [&](int segbase, int NTseg, int ks0, int nks, int ntw) {
        #pragma unroll 1
        for (int ks = 0; ks < nks; ++ks) {
            const uint2* bp = &gWB[segbase + ((ks0 + ks) * NTseg + ntw) * 2][lane];
            uint2 bh[8], bl[8];
            #pragma unroll
            for (int j = 0; j < 8; ++j) { bh[j] = __ldg(bp + j*64); bl[j] = __ldg(bp + j*64 + 32); }
            uint32_t ah[2][4], al[2][4];
            #pragma unroll
            for (int mt = 0; mt < 2; ++mt) {
                uint32_t off = (uint32_t)(((arow + mt*16) * LDX + ks*16 + kadd) * 2);
                LDSM_X4(ah[mt][0], ah[mt][1], ah[mt][2], ah[mt][3], xh + off);
                LDSM_X4(al[mt][0], al[mt][1], al[mt][2], al[mt][3], xl + off);
            }
            #pragma unroll
            for (int mt = 0; mt < 2; ++mt)
                #pragma unroll
                for (int j = 0; j < 8; ++j) MMA_BF16(C[mt][j], ah[mt], bh[j].x, bh[j].y);
            #pragma unroll
            for (int mt = 0; mt < 2; ++mt)
                #pragma unroll
                for (int j = 0; j < 8; ++j) MMA_BF16(C[mt][j], ah[mt], bl[j].x, bl[j].y);
            #pragma unroll
            for (int mt = 0; mt < 2; ++mt)
                #pragma unroll
                for (int j = 0; j < 8; ++j) MMA_BF16(C[mt][j], al[mt], bh[j].x, bh[j].y);
        }
    };

    // ---- layer-1 pre-mix: X_mixed = A1 @ x, gathered from gmem, split to XH/XL ----
    auto premix_x = [&](int kc) {
        __syncthreads();
        #pragma unroll 1
        for (int idx = tid; idx < 4096; idx += 256) {
            int r = idx >> 5, q = idx & 31;
            float4 s = make_float4(0.f, 0.f, 0.f, 0.f);
            if (r < rows_valid) {
                int n = rown[r];
                const int gbr = b0row + r - n;
                const int base = n * ANN, cnt = Acnt[n];
                for (int e = 0; e < cnt; ++e) {
                    float a = Aw[base + e];
                    const float4 v = __ldg((const float4*)(x + (size_t)(gbr + Ai[base+e]) * 256 + kc*128) + q);
                    s.x = fmaf(a, v.x, s.x); s.y = fmaf(a, v.y, s.y);
                    s.z = fmaf(a, v.z, s.z); s.w = fmaf(a, v.w, s.w);
                }
            }
            float h0 = __bfloat162float(__float2bfloat16(s.x));
            float h1 = __bfloat162float(__float2bfloat16(s.y));
            float h2 = __bfloat162float(__float2bfloat16(s.z));
            float h3 = __bfloat162float(__float2bfloat16(s.w));
            *(uint2*)(XH + r*LDX + q*4) = make_uint2(pack_bf2(h0, h1), pack_bf2(h2, h3));
            *(uint2*)(XL + r*LDX + q*4) =
                make_uint2(pack_bf2(s.x - h0, s.y - h1), pack_bf2(s.z - h2, s.w - h3));
        }
        __syncthreads();
    };

    // ---- layers 1/2 epilogue: bias+relu from regs -> split store, then
    //      in-place pre-mix with NEXT layer's A (chunked, 32 cols at a time) ----
    auto epi12 = [&](const float* __restrict__ bias, int Lnext) {
        __syncthreads();   // all warps done reading XH/XL
        #pragma unroll
        for (int mt = 0; mt < 2; ++mt)
            #pragma unroll
            for (int j = 0; j < 8; ++j) {
                int c  = ng*64 + j*8 + (lane&3)*2;
                float2 bb = __ldg((const float2*)(bias + c));
                int r0 = m0base + mt*16 + (lane>>2);
                float v00 = fmaxf(C[mt][j][0] + bb.x, 0.f);
                float v01 = fmaxf(C[mt][j][1] + bb.y, 0.f);
                float v10 = fmaxf(C[mt][j][2] + bb.x, 0.f);
                float v11 = fmaxf(C[mt][j][3] + bb.y, 0.f);
                float h00 = __bfloat162float(__float2bfloat16(v00));
                float h01 = __bfloat162float(__float2bfloat16(v01));
                float h10 = __bfloat162float(__float2bfloat16(v10));
                float h11 = __bfloat162float(__float2bfloat16(v11));
                *(uint32_t*)(XH + r0*LDX + c)     = pack_bf2(h00, h01);
                *(uint32_t*)(XL + r0*LDX + c)     = pack_bf2(v00 - h00, v01 - h01);
                *(uint32_t*)(XH + (r0+8)*LDX + c) = pack_bf2(h10, h11);
                *(uint32_t*)(XL + (r0+8)*LDX + c) = pack_bf2(v10 - h10, v11 - h11);
            }
        __syncthreads();
        #pragma unroll 1
        for (int ch = 0; ch < 4; ++ch) {
            float mv[16];
            #pragma unroll
            for (int t = 0; t < 16; ++t) {
                int idx = tid + t*256;
                int r = idx >> 5, c = (idx & 31) + ch*32;
                float s = 0.f;
                if (r < rows_valid) {
                    int n = rown[r], gb0 = r - n;
                    int base = (Lnext*21 + n)*ANN, cnt = Acnt[Lnext*21 + n];
                    for (int e = 0; e < cnt; ++e) {
                        int off = (gb0 + Ai[base+e]) * LDX + c;
                        s = fmaf(Aw[base+e],
                                 __bfloat162float(XH[off]) + __bfloat162float(XL[off]), s);
                    }
                }
                mv[t] = s;
            }
            __syncthreads();
            #pragma unroll
            for (int t = 0; t < 16; ++t) {
                int idx = tid + t*256;
                int r = idx >> 5, c = (idx & 31) + ch*32;
                float hi = __bfloat162float(__float2bfloat16(mv[t]));
                XH[r*LDX + c] = __float2bfloat16(hi);
                XL[r*LDX + c] = __float2bfloat16(mv[t] - hi);
            }
            __syncthreads();
        }
    };

    // ================= Layer 1: K=256 (2 pre-mixed chunks) =================
    ZERO_C();
    premix_x(0);
    sweepK(SEG_W1, 16, 0, 8, ng*8);
    premix_x(1);
    sweepK(SEG_W1, 16, 8, 8, ng*8);
    epi12(b1, 1);          // -> A2-premixed x1 in XH/XL

    // ================= Layer 2: K=128 =================
    ZERO_C();
    sweepK(SEG_W2, 16, 0, 8, ng*8);
    epi12(b2, 2);          // -> A3-premixed x2 in XH/XL

    // ================= Layer 3: K=128, N=512 (4 n-chunks), all-register epi ====
    #pragma unroll 1
    for (int nc = 0; nc < 4; ++nc) {
        ZERO_C();
        sweepK(SEG_W3, 64, 0, 8, nc*16 + ng*8);
        float facc[12];
        #pragma unroll
        for (int i = 0; i < 12; ++i) facc[i] = 0.f;
        #pragma unroll
        for (int mt = 0; mt < 2; ++mt)
            #pragma unroll
            for (int j = 0; j < 8; ++j) {
                int cg = nc*128 + ng*64 + j*8 + (lane&3)*2;
                float2 bb = __ldg((const float2*)(b3 + cg));
                int r0 = m0base + mt*16 + (lane>>2);
                bool ok0 = (r0     < rows_valid);
                bool ok1 = (r0 + 8 < rows_valid);
                float v00 = ok0 ? fmaxf(C[mt][j][0] + bb.x, 0.f) : 0.f;
                float v01 = ok0 ? fmaxf(C[mt][j][1] + bb.y, 0.f) : 0.f;
                float v10 = ok1 ? fmaxf(C[mt][j][2] + bb.x, 0.f) : 0.f;
                float v11 = ok1 ? fmaxf(C[mt][j][3] + bb.y, 0.f) : 0.f;
                if (ok0) *(float2*)(x3g + (size_t)(b0row + r0    )*512 + cg) = make_float2(v00, v01);
                if (ok1) *(float2*)(x3g + (size_t)(b0row + r0 + 8)*512 + cg) = make_float2(v10, v11);
                #pragma unroll
                for (int jo = 0; jo < 3; ++jo) {
                    float w0 = __ldg(fcW + (size_t)cg*3 + jo);
                    float w1 = __ldg(fcW + (size_t)(cg+1)*3 + jo);
                    facc[(mt*2+0)*3 + jo] += v00*w0 + v01*w1;
                    facc[(mt*2+1)*3 + jo] += v10*w0 + v11*w1;
                }
            }
        #pragma unroll
        for (int i = 0; i < 12; ++i) {
            facc[i] += __shfl_xor_sync(0xFFFFFFFF, facc[i], 1);
            facc[i] += __shfl_xor_sync(0xFFFFFFFF, facc[i], 2);
        }
        if ((lane & 3) == 0) {
            #pragma unroll
            for (int mt = 0; mt < 2; ++mt)
                #pragma unroll
                for (int rh = 0; rh < 2; ++rh) {
                    int r = m0base + mt*16 + (lane>>2) + rh*8;
                    if (r < rows_valid) {
                        #pragma unroll
                        for (int jo = 0; jo < 3; ++jo)
                            atomicAdd(&Oac[r*3 + jo], facc[(mt*2+rh)*3 + jo]);
                    }
                }
        }
    }

    // ---- final out = FC + fcb ----
    __syncthreads();
    for (int w = tid; w < 378; w += 256) {
        int r = w / 3, j = w - 3*r;
        if (r < rows_valid)
            outg[(size_t)(b0row + r)*3 + j] = Oac[w] + __ldg(fcb + j);
    }
    #undef ZERO_C
}

extern "C" void kernel_launch(void* const* d_in, const int* in_sizes, int n_in,
                              void* d_out, int out_size) {
    const float* x   = (const float*)d_in[0];
    const float* A1  = (const float*)d_in[1];
    const float* A2  = (const float*)d_in[2];
    const float* A3  = (const float*)d_in[3];
    const float* W1  = (const float*)d_in[4];
    const float* b1  = (const float*)d_in[5];
    const float* W2  = (const float*)d_in[6];
    const float* b2  = (const float*)d_in[7];
    const float* W3  = (const float*)d_in[8];
    const float* b3  = (const float*)d_in[9];
    const float* fcW = (const float*)d_in[10];
    const float* fcb = (const float*)d_in[11];

    const int Btot = in_sizes[0] / (21 * 256);
    float* x3g  = (float*)d_out;
    float* outg = x3g + (size_t)Btot * 21 * 512;

    static int attr_done = 0;
    if (!attr_done) {
        cudaFuncSetAttribute(handnet_mma, cudaFuncAttributeMaxDynamicSharedMemorySize, SMEM_SZ);
        attr_done = 1;
    }

    prep_frags<<<NFRAG, 32>>>(W1, W2, W3);
    const int nCTA = (Btot * 21 + 125) / 126;
    handnet_mma<<<nCTA, 256, SMEM_SZ>>>(x, A1, A2, A3, b1, b2, b3, fcW, fcb,
                                        x3g, outg, Btot);
}

// round 7
// speedup vs baseline: 2.4244x; 1.2630x over previous
#include <cuda_runtime.h>
#include <cuda_bf16.h>
#include <cstdint>

// ============================================================
// Portable-PTX (base sm_103) tensor path: ldmatrix + mma.sync bf16
// + cp.async smem pipeline for B fragments
// ============================================================
__device__ __forceinline__ uint32_t smem_u32(const void* p) {
    uint32_t a;
    asm("{ .reg .u64 t; cvta.to.shared.u64 t, %1; cvt.u32.u64 %0, t; }" : "=r"(a) : "l"(p));
    return a;
}
#define LDSM_X4(a0,a1,a2,a3,addr) \
    asm volatile("ldmatrix.sync.aligned.m8n8.x4.shared.b16 {%0,%1,%2,%3}, [%4];" \
        : "=r"(a0), "=r"(a1), "=r"(a2), "=r"(a3) : "r"(addr))
#define MMA_BF16(c, a, b0, b1) \
    asm volatile("mma.sync.aligned.m16n8k16.row.col.f32.bf16.bf16.f32 " \
        "{%0,%1,%2,%3}, {%4,%5,%6,%7}, {%8,%9}, {%0,%1,%2,%3};" \
        : "+f"((c)[0]), "+f"((c)[1]), "+f"((c)[2]), "+f"((c)[3]) \
        : "r"((a)[0]), "r"((a)[1]), "r"((a)[2]), "r"((a)[3]), "r"(b0), "r"(b1))
__device__ __forceinline__ void cp16(uint32_t dst, const void* src) {
    asm volatile("cp.async.ca.shared.global [%0], [%1], 16;" :: "r"(dst), "l"(src));
}
#define CP_COMMIT()  asm volatile("cp.async.commit_group;" ::: "memory")
#define CP_WAIT(n)   asm volatile("cp.async.wait_group %0;" :: "n"(n) : "memory")

namespace {
constexpr int LDX = 136;        // bf16 row stride (272 B = 17*16B -> LDSM conflict-free)
constexpr int ANN = 12;         // max nnz per A row
// dynamic smem offsets
constexpr int OFF_XH   = 0;              // [128][136] bf16 = 34816
constexpr int OFF_XL   = 34816;          // [128][136] bf16 = 34816
constexpr int OFF_B    = 69632;          // 3 x 8192 B ring  = 24576
constexpr int OFF_AW   = 94208;          // [3][21][12] f32  = 3024
constexpr int OFF_AI   = 97232;          // [3][21][12] u8   = 768
constexpr int OFF_ACNT = 98000;          // i32[64] = 256
constexpr int OFF_OAC  = 98256;          // f32[384] = 1536
constexpr int OFF_ROWN = 99792;          // u8[128]
constexpr int SMEM_SZ  = 99968;
// B-fragment segment bases (fragset units; 1 fragset = 32 lanes * 8 B = 256 B)
constexpr int SEG_W1 = 0;      // 16 ks * 16 nt * 2 parts = 512
constexpr int SEG_W2 = 512;    //  8 ks * 16 nt * 2       = 256
constexpr int SEG_W3 = 768;    //  8 ks * 64 nt * 2       = 1024
constexpr int NFRAG  = 1792;
} // namespace

// Per-lane precomputed B fragments (bf16x2 pairs), hi/lo parts.
// For one k-step the CTA's 32 fragsets are CONTIGUOUS (8 KB) -> bulk cp.async.
__device__ __align__(16) uint2 gWB[NFRAG][32];

__device__ __forceinline__ uint32_t pack_bf2(float x, float y) {
    __nv_bfloat162 h = __floats2bfloat162_rn(x, y);
    return *reinterpret_cast<uint32_t*>(&h);
}

// Expand W into mma B-fragment layout: fragset id = seg + (ks*NT + nt)*2 + part.
__global__ void prep_frags(const float* __restrict__ W1,
                           const float* __restrict__ W2,
                           const float* __restrict__ W3) {
    const int id = blockIdx.x, l = threadIdx.x;
    const float* W; int ld, r;
    if (id < 512)      { W = W1; ld = 128; r = id; }
    else if (id < 768) { W = W2; ld = 128; r = id - 512; }
    else               { W = W3; ld = 512; r = id - 768; }
    const int part = r & 1; r >>= 1;
    const int NT = (id < 768) ? 16 : 64;
    const int nt = r % NT, ks = r / NT;
    const int n  = nt * 8 + (l >> 2);
    const int k0 = ks * 16 + (l & 3) * 2;

    float v[4];
    #pragma unroll
    for (int i = 0; i < 4; ++i) {
        int k = k0 + (i >> 1) * 8 + (i & 1);
        float w = W[(size_t)k * ld + n];
        float hi = __bfloat162float(__float2bfloat16(w));
        v[i] = part ? (w - hi) : hi;
    }
    gWB[id][l] = make_uint2(pack_bf2(v[0], v[1]), pack_bf2(v[2], v[3]));
}

__global__ void __launch_bounds__(256, 2)
handnet_mma(const float* __restrict__ x,
            const float* __restrict__ A1, const float* __restrict__ A2,
            const float* __restrict__ A3,
            const float* __restrict__ b1, const float* __restrict__ b2,
            const float* __restrict__ b3,
            const float* __restrict__ fcW, const float* __restrict__ fcb,
            float* __restrict__ x3g, float* __restrict__ outg, int Btot)
{
    extern __shared__ unsigned char sm[];
    __nv_bfloat16* XH = (__nv_bfloat16*)(sm + OFF_XH);
    __nv_bfloat16* XL = (__nv_bfloat16*)(sm + OFF_XL);
    float*   Aw   = (float*)(sm + OFF_AW);
    uint8_t* Ai   = sm + OFF_AI;
    int*     Acnt = (int*)(sm + OFF_ACNT);
    float*   Oac  = (float*)(sm + OFF_OAC);
    uint8_t* rown = sm + OFF_ROWN;

    const int tid = threadIdx.x, lane = tid & 31, wid = tid >> 5;
    const int mg = wid >> 1, ng = wid & 1;           // 4 m-groups x 2 n-groups
    const int m0base = mg * 32;
    const int arow = m0base + (lane & 7) + ((lane >> 3) & 1) * 8;
    const int kadd = ((lane >> 4) & 1) * 8;
    const uint32_t xh = smem_u32(XH), xl = smem_u32(XL);
    const uint32_t smB = smem_u32(sm + OFF_B);

    const int b0row = blockIdx.x * 126;
    const int rows_valid = min(126, Btot * 21 - b0row);

    // ---- setup: LUTs, sparse A lists, Oac zero ----
    if (tid < 128) rown[tid] = (uint8_t)(tid % 21);
    if (tid < 63) {
        int L = tid / 21, n = tid % 21;
        const float* A = (L == 0) ? A1 : ((L == 1) ? A2 : A3);
        int c = 0;
        for (int m = 0; m < 21 && c < ANN; ++m) {
            float v = __ldg(A + n * 21 + m);
            if (v != 0.f) { Aw[(L*21+n)*ANN + c] = v; Ai[(L*21+n)*ANN + c] = (uint8_t)m; ++c; }
        }
        Acnt[L * 21 + n] = c;
    }
    for (int i = tid; i < 384; i += 256) Oac[i] = 0.f;
    __syncthreads();

    float C[2][8][4];
    #define ZERO_C() { _Pragma("unroll") for (int mt=0;mt<2;++mt) _Pragma("unroll") \
        for (int j=0;j<8;++j) { C[mt][j][0]=0.f;C[mt][j][1]=0.f;C[mt][j][2]=0.f;C[mt][j][3]=0.f; } }

    // cooperative 8 KB fragment load for one k-step -> ring buffer slot
    auto ldB = [&](int fragbase, int slot) {
        const char* src = (const char*)&gWB[fragbase][0] + tid * 32;
        uint32_t dst = smB + (uint32_t)slot * 8192u + (uint32_t)tid * 32u;
        cp16(dst, src);
        cp16(dst + 16, src + 16);
        CP_COMMIT();
    };

    // ---- pipelined 3-pass GEMM sweep; B via cp.async ring (3 slots) ----
    // fragbase0: fragset index of k-step ks0; stride: fragsets per k-step row.
    auto sweepK = [&](int fragbase0, int stride, int nks) {
        __syncthreads();                       // retire stale Bbuf readers
        ldB(fragbase0, 0);                     // prologue: k-step 0 -> slot 0
        #pragma unroll 1
        for (int ks = 0; ks < nks; ++ks) {
            if (ks + 1 < nks) { ldB(fragbase0 + (ks+1)*stride, (ks+1) % 3); CP_WAIT(1); }
            else              { CP_WAIT(0); }
            __syncthreads();                   // slot ks%3 visible to all warps
            uint32_t ah[2][4], al[2][4];
            #pragma unroll
            for (int mt = 0; mt < 2; ++mt) {
                uint32_t off = (uint32_t)(((arow + mt*16) * LDX + ks*16 + kadd) * 2);
                LDSM_X4(ah[mt][0], ah[mt][1], ah[mt][2], ah[mt][3], xh + off);
                LDSM_X4(al[mt][0], al[mt][1], al[mt][2], al[mt][3], xl + off);
            }
            const unsigned char* bslot = sm + OFF_B + (ks % 3) * 8192 + lane * 8;
            #pragma unroll
            for (int j = 0; j < 8; ++j) {
                const unsigned char* bp = bslot + (ng*16 + j*2) * 256;
                uint2 bh = *(const uint2*)bp;
                uint2 bl = *(const uint2*)(bp + 256);
                #pragma unroll
                for (int mt = 0; mt < 2; ++mt) {
                    MMA_BF16(C[mt][j], ah[mt], bh.x, bh.y);
                    MMA_BF16(C[mt][j], ah[mt], bl.x, bl.y);
                    MMA_BF16(C[mt][j], al[mt], bh.x, bh.y);
                }
            }
        }
    };

    // ---- layer-1 pre-mix: X_mixed = A1 @ x, gathered from gmem, split hi/lo ----
    auto premix_x = [&](int kc) {
        __syncthreads();
        #pragma unroll 1
        for (int idx = tid; idx < 4096; idx += 256) {
            int r = idx >> 5, q = idx & 31;
            float4 s = make_float4(0.f, 0.f, 0.f, 0.f);
            if (r < rows_valid) {
                int n = rown[r];
                const int gbr = b0row + r - n;
                const int base = n * ANN, cnt = Acnt[n];
                for (int e = 0; e < cnt; ++e) {
                    float a = Aw[base + e];
                    const float4 v = __ldg((const float4*)(x + (size_t)(gbr + Ai[base+e]) * 256 + kc*128) + q);
                    s.x = fmaf(a, v.x, s.x); s.y = fmaf(a, v.y, s.y);
                    s.z = fmaf(a, v.z, s.z); s.w = fmaf(a, v.w, s.w);
                }
            }
            float h0 = __bfloat162float(__float2bfloat16(s.x));
            float h1 = __bfloat162float(__float2bfloat16(s.y));
            float h2 = __bfloat162float(__float2bfloat16(s.z));
            float h3 = __bfloat162float(__float2bfloat16(s.w));
            *(uint2*)(XH + r*LDX + q*4) = make_uint2(pack_bf2(h0, h1), pack_bf2(h2, h3));
            *(uint2*)(XL + r*LDX + q*4) =
                make_uint2(pack_bf2(s.x - h0, s.y - h1), pack_bf2(s.z - h2, s.w - h3));
        }
        __syncthreads();
    };

    // ---- layers 1/2 epilogue: bias+relu -> split store, then in-place
    //      pre-mix with NEXT layer's A (chunked 32 cols) ----
    auto epi12 = [&](const float* __restrict__ bias, int Lnext) {
        __syncthreads();
        #pragma unroll
        for (int mt = 0; mt < 2; ++mt)
            #pragma unroll
            for (int j = 0; j < 8; ++j) {
                int c  = ng*64 + j*8 + (lane&3)*2;
                float2 bb = __ldg((const float2*)(bias + c));
                int r0 = m0base + mt*16 + (lane>>2);
                float v00 = fmaxf(C[mt][j][0] + bb.x, 0.f);
                float v01 = fmaxf(C[mt][j][1] + bb.y, 0.f);
                float v10 = fmaxf(C[mt][j][2] + bb.x, 0.f);
                float v11 = fmaxf(C[mt][j][3] + bb.y, 0.f);
                float h00 = __bfloat162float(__float2bfloat16(v00));
                float h01 = __bfloat162float(__float2bfloat16(v01));
                float h10 = __bfloat162float(__float2bfloat16(v10));
                float h11 = __bfloat162float(__float2bfloat16(v11));
                *(uint32_t*)(XH + r0*LDX + c)     = pack_bf2(h00, h01);
                *(uint32_t*)(XL + r0*LDX + c)     = pack_bf2(v00 - h00, v01 - h01);
                *(uint32_t*)(XH + (r0+8)*LDX + c) = pack_bf2(h10, h11);
                *(uint32_t*)(XL + (r0+8)*LDX + c) = pack_bf2(v10 - h10, v11 - h11);
            }
        __syncthreads();
        #pragma unroll 1
        for (int ch = 0; ch < 4; ++ch) {
            float mv[16];
            #pragma unroll
            for (int t = 0; t < 16; ++t) {
                int idx = tid + t*256;
                int r = idx >> 5, c = (idx & 31) + ch*32;
                float s = 0.f;
                if (r < rows_valid) {
                    int n = rown[r], gb0 = r - n;
                    int base = (Lnext*21 + n)*ANN, cnt = Acnt[Lnext*21 + n];
                    for (int e = 0; e < cnt; ++e) {
                        int off = (gb0 + Ai[base+e]) * LDX + c;
                        s = fmaf(Aw[base+e],
                                 __bfloat162float(XH[off]) + __bfloat162float(XL[off]), s);
                    }
                }
                mv[t] = s;
            }
            __syncthreads();
            #pragma unroll
            for (int t = 0; t < 16; ++t) {
                int idx = tid + t*256;
                int r = idx >> 5, c = (idx & 31) + ch*32;
                float hi = __bfloat162float(__float2bfloat16(mv[t]));
                XH[r*LDX + c] = __float2bfloat16(hi);
                XL[r*LDX + c] = __float2bfloat16(mv[t] - hi);
            }
            __syncthreads();
        }
    };

    // ================= Layer 1: K=256 (2 pre-mixed chunks) =================
    ZERO_C();
    premix_x(0);
    sweepK(SEG_W1 + 0*32, 32, 8);
    premix_x(1);
    sweepK(SEG_W1 + 8*32, 32, 8);
    epi12(b1, 1);          // -> A2-premixed x1 in XH/XL

    // ================= Layer 2: K=128 =================
    ZERO_C();
    sweepK(SEG_W2, 32, 8);
    epi12(b2, 2);          // -> A3-premixed x2 in XH/XL

    // ================= Layer 3: K=128, N=512 (4 n-chunks), register epi =====
    #pragma unroll 1
    for (int nc = 0; nc < 4; ++nc) {
        ZERO_C();
        sweepK(SEG_W3 + nc*32, 128, 8);
        float facc[12];
        #pragma unroll
        for (int i = 0; i < 12; ++i) facc[i] = 0.f;
        #pragma unroll
        for (int mt = 0; mt < 2; ++mt)
            #pragma unroll
            for (int j = 0; j < 8; ++j) {
                int cg = nc*128 + ng*64 + j*8 + (lane&3)*2;
                float2 bb = __ldg((const float2*)(b3 + cg));
                int r0 = m0base + mt*16 + (lane>>2);
                bool ok0 = (r0     < rows_valid);
                bool ok1 = (r0 + 8 < rows_valid);
                float v00 = ok0 ? fmaxf(C[mt][j][0] + bb.x, 0.f) : 0.f;
                float v01 = ok0 ? fmaxf(C[mt][j][1] + bb.y, 0.f) : 0.f;
                float v10 = ok1 ? fmaxf(C[mt][j][2] + bb.x, 0.f) : 0.f;
                float v11 = ok1 ? fmaxf(C[mt][j][3] + bb.y, 0.f) : 0.f;
                if (ok0) *(float2*)(x3g + (size_t)(b0row + r0    )*512 + cg) = make_float2(v00, v01);
                if (ok1) *(float2*)(x3g + (size_t)(b0row + r0 + 8)*512 + cg) = make_float2(v10, v11);
                #pragma unroll
                for (int jo = 0; jo < 3; ++jo) {
                    float w0 = __ldg(fcW + (size_t)cg*3 + jo);
                    float w1 = __ldg(fcW + (size_t)(cg+1)*3 + jo);
                    facc[(mt*2+0)*3 + jo] += v00*w0 + v01*w1;
                    facc[(mt*2+1)*3 + jo] += v10*w0 + v11*w1;
                }
            }
        #pragma unroll
        for (int i = 0; i < 12; ++i) {
            facc[i] += __shfl_xor_sync(0xFFFFFFFF, facc[i], 1);
            facc[i] += __shfl_xor_sync(0xFFFFFFFF, facc[i], 2);
        }
        if ((lane & 3) == 0) {
            #pragma unroll
            for (int mt = 0; mt < 2; ++mt)
                #pragma unroll
                for (int rh = 0; rh < 2; ++rh) {
                    int r = m0base + mt*16 + (lane>>2) + rh*8;
                    if (r < rows_valid) {
                        #pragma unroll
                        for (int jo = 0; jo < 3; ++jo)
                            atomicAdd(&Oac[r*3 + jo], facc[(mt*2+rh)*3 + jo]);
                    }
                }
        }
    }

    // ---- final out = FC + fcb ----
    __syncthreads();
    for (int w = tid; w < 378; w += 256) {
        int r = w / 3, j = w - 3*r;
        if (r < rows_valid)
            outg[(size_t)(b0row + r)*3 + j] = Oac[w] + __ldg(fcb + j);
    }
    #undef ZERO_C
}

extern "C" void kernel_launch(void* const* d_in, const int* in_sizes, int n_in,
                              void* d_out, int out_size) {
    const float* x   = (const float*)d_in[0];
    const float* A1  = (const float*)d_in[1];
    const float* A2  = (const float*)d_in[2];
    const float* A3  = (const float*)d_in[3];
    const float* W1  = (const float*)d_in[4];
    const float* b1  = (const float*)d_in[5];
    const float* W2  = (const float*)d_in[6];
    const float* b2  = (const float*)d_in[7];
    const float* W3  = (const float*)d_in[8];
    const float* b3  = (const float*)d_in[9];
    const float* fcW = (const float*)d_in[10];
    const float* fcb = (const float*)d_in[11];

    const int Btot = in_sizes[0] / (21 * 256);
    float* x3g  = (float*)d_out;
    float* outg = x3g + (size_t)Btot * 21 * 512;

    static int attr_done = 0;
    if (!attr_done) {
        cudaFuncSetAttribute(handnet_mma, cudaFuncAttributeMaxDynamicSharedMemorySize, SMEM_SZ);
        attr_done = 1;
    }

    prep_frags<<<NFRAG, 32>>>(W1, W2, W3);
    const int nCTA = (Btot * 21 + 125) / 126;
    handnet_mma<<<nCTA, 256, SMEM_SZ>>>(x, A1, A2, A3, b1, b2, b3, fcW, fcb,
                                        x3g, outg, Btot);
}

// round 8
// speedup vs baseline: 2.4703x; 1.0189x over previous
#include <cuda_runtime.h>
#include <cuda_bf16.h>
#include <cstdint>

// ============================================================
// Portable-PTX (base sm_103) tensor path: ldmatrix + mma.sync bf16
// + cp.async 2-slot unit-pipelined B fragments (1 barrier / 2 k-steps)
// ============================================================
__device__ __forceinline__ uint32_t smem_u32(const void* p) {
    uint32_t a;
    asm("{ .reg .u64 t; cvta.to.shared.u64 t, %1; cvt.u32.u64 %0, t; }" : "=r"(a) : "l"(p));
    return a;
}
#define LDSM_X4(a0,a1,a2,a3,addr) \
    asm volatile("ldmatrix.sync.aligned.m8n8.x4.shared.b16 {%0,%1,%2,%3}, [%4];" \
        : "=r"(a0), "=r"(a1), "=r"(a2), "=r"(a3) : "r"(addr))
#define MMA_BF16(c, a, b0, b1) \
    asm volatile("mma.sync.aligned.m16n8k16.row.col.f32.bf16.bf16.f32 " \
        "{%0,%1,%2,%3}, {%4,%5,%6,%7}, {%8,%9}, {%0,%1,%2,%3};" \
        : "+f"((c)[0]), "+f"((c)[1]), "+f"((c)[2]), "+f"((c)[3]) \
        : "r"((a)[0]), "r"((a)[1]), "r"((a)[2]), "r"((a)[3]), "r"(b0), "r"(b1))
__device__ __forceinline__ void cp16(uint32_t dst, const void* src) {
    asm volatile("cp.async.ca.shared.global [%0], [%1], 16;" :: "r"(dst), "l"(src));
}
#define CP_COMMIT()  asm volatile("cp.async.commit_group;" ::: "memory")
#define CP_WAIT(n)   asm volatile("cp.async.wait_group %0;" :: "n"(n) : "memory")

namespace {
constexpr int LDX = 136;        // bf16 row stride (272 B = 17*16B -> LDSM conflict-free)
constexpr int ANN = 12;         // max nnz per A row
// dynamic smem offsets
constexpr int OFF_XH   = 0;              // [128][136] bf16 = 34816
constexpr int OFF_XL   = 34816;          // [128][136] bf16 = 34816
constexpr int OFF_B    = 69632;          // 2 slots x 16384  = 32768
constexpr int OFF_AW   = 102400;         // [3][21][12] f32  = 3024
constexpr int OFF_AI   = 105424;         // [3][21][12] u8   = 768
constexpr int OFF_ACNT = 106192;         // i32[64] = 256
constexpr int OFF_OAC  = 106448;         // f32[384] = 1536
constexpr int OFF_ROWN = 107984;         // u8[128]
constexpr int SMEM_SZ  = 108160;
// fragPAIR bases (1 pair = hi+lo for one (kstep, n-tile); 512 B = 32 lanes x 16 B)
constexpr int PAIR_W1 = 0;      // 16 ks * 16 nt = 256
constexpr int PAIR_W2 = 256;    //  8 ks * 16 nt = 128
constexpr int PAIR_W3 = 384;    //  8 ks * 64 nt = 512
constexpr int NPAIR   = 896;
} // namespace

// Per-lane B fragments, hi/lo interleaved: [pair][lane] = {hi.x, hi.y, lo.x, lo.y}.
// Per k-step the CTA's 16 pairs are contiguous (8 KB) -> bulk cp.async.
__device__ __align__(16) uint4 gWB[NPAIR][32];

__device__ __forceinline__ uint32_t pack_bf2(float x, float y) {
    __nv_bfloat162 h = __floats2bfloat162_rn(x, y);
    return *reinterpret_cast<uint32_t*>(&h);
}

// Expand W into paired fragment layout. pair id = base + ks*NT + nt.
__global__ void prep_frags(const float* __restrict__ W1,
                           const float* __restrict__ W2,
                           const float* __restrict__ W3) {
    const int id = blockIdx.x, l = threadIdx.x;
    const float* W; int ld, r, NT;
    if (id < 256)      { W = W1; ld = 128; r = id;       NT = 16; }
    else if (id < 384) { W = W2; ld = 128; r = id - 256; NT = 16; }
    else               { W = W3; ld = 512; r = id - 384; NT = 64; }
    const int nt = r % NT, ks = r / NT;
    const int n  = nt * 8 + (l >> 2);
    const int k0 = ks * 16 + (l & 3) * 2;

    float h[4], lo[4];
    #pragma unroll
    for (int i = 0; i < 4; ++i) {
        int k = k0 + (i >> 1) * 8 + (i & 1);
        float w = W[(size_t)k * ld + n];
        h[i]  = __bfloat162float(__float2bfloat16(w));
        lo[i] = w - h[i];
    }
    gWB[id][l] = make_uint4(pack_bf2(h[0], h[1]),  pack_bf2(h[2], h[3]),
                            pack_bf2(lo[0], lo[1]), pack_bf2(lo[2], lo[3]));
}

__global__ void __launch_bounds__(256, 2)
handnet_mma(const float* __restrict__ x,
            const float* __restrict__ A1, const float* __restrict__ A2,
            const float* __restrict__ A3,
            const float* __restrict__ b1, const float* __restrict__ b2,
            const float* __restrict__ b3,
            const float* __restrict__ fcW, const float* __restrict__ fcb,
            float* __restrict__ x3g, float* __restrict__ outg, int Btot)
{
    extern __shared__ unsigned char sm[];
    __nv_bfloat16* XH = (__nv_bfloat16*)(sm + OFF_XH);
    __nv_bfloat16* XL = (__nv_bfloat16*)(sm + OFF_XL);
    float*   Aw   = (float*)(sm + OFF_AW);
    uint8_t* Ai   = sm + OFF_AI;
    int*     Acnt = (int*)(sm + OFF_ACNT);
    float*   Oac  = (float*)(sm + OFF_OAC);
    uint8_t* rown = sm + OFF_ROWN;

    const int tid = threadIdx.x, lane = tid & 31, wid = tid >> 5;
    const int mg = wid >> 1, ng = wid & 1;           // 4 m-groups x 2 n-groups
    const int m0base = mg * 32;
    const int arow = m0base + (lane & 7) + ((lane >> 3) & 1) * 8;
    const int kadd = ((lane >> 4) & 1) * 8;
    const uint32_t xh = smem_u32(XH), xl = smem_u32(XL);
    const uint32_t smB = smem_u32(sm + OFF_B);

    const int b0row = blockIdx.x * 126;
    const int rows_valid = min(126, Btot * 21 - b0row);

    // ---- setup ----
    if (tid < 128) rown[tid] = (uint8_t)(tid % 21);
    if (tid < 63) {
        int L = tid / 21, n = tid % 21;
        const float* A = (L == 0) ? A1 : ((L == 1) ? A2 : A3);
        int c = 0;
        for (int m = 0; m < 21 && c < ANN; ++m) {
            float v = __ldg(A + n * 21 + m);
            if (v != 0.f) { Aw[(L*21+n)*ANN + c] = v; Ai[(L*21+n)*ANN + c] = (uint8_t)m; ++c; }
        }
        Acnt[L * 21 + n] = c;
    }
    for (int i = tid; i < 384; i += 256) Oac[i] = 0.f;
    __syncthreads();

    float C[2][8][4];
    #define ZERO_C() { _Pragma("unroll") for (int mt=0;mt<2;++mt) _Pragma("unroll") \
        for (int j=0;j<8;++j) { C[mt][j][0]=0.f;C[mt][j][1]=0.f;C[mt][j][2]=0.f;C[mt][j][3]=0.f; } }

    // cooperative load of one 2-kstep unit (2 x 8 KB) into a slot
    auto ldBunit = [&](int pb, int pstride, int slot) {
        #pragma unroll
        for (int h = 0; h < 2; ++h) {
            const char* src = (const char*)&gWB[pb + h * pstride][0] + tid * 32;
            uint32_t dst = smB + (uint32_t)slot * 16384u + (uint32_t)h * 8192u
                               + (uint32_t)tid * 32u;
            cp16(dst, src);
            cp16(dst + 16, src + 16);
        }
        CP_COMMIT();
    };

    // ---- pipelined sweep: 8 ksteps = 4 units; 1 barrier per unit; loads
    //      of unit u+1 overlap compute of unit u (2-slot, race-free) ----
    auto sweepK = [&](int pairbase, int pstride) {
        __syncthreads();                          // prev readers of slot0 done
        ldBunit(pairbase, pstride, 0);
        #pragma unroll 1
        for (int u = 0; u < 4; ++u) {
            CP_WAIT(0);
            __syncthreads();                      // slot u&1 ready; slot (u+1)&1 free
            if (u < 3) ldBunit(pairbase + (u + 1) * 2 * pstride, pstride, (u + 1) & 1);
            #pragma unroll
            for (int k2 = 0; k2 < 2; ++k2) {
                const int ks = u * 2 + k2;
                uint32_t ah[2][4], al[2][4];
                #pragma unroll
                for (int mt = 0; mt < 2; ++mt) {
                    uint32_t off = (uint32_t)(((arow + mt*16) * LDX + ks*16 + kadd) * 2);
                    LDSM_X4(ah[mt][0], ah[mt][1], ah[mt][2], ah[mt][3], xh + off);
                    LDSM_X4(al[mt][0], al[mt][1], al[mt][2], al[mt][3], xl + off);
                }
                const unsigned char* bp0 = sm + OFF_B + (u & 1) * 16384 + k2 * 8192
                                             + ng * 8 * 512 + lane * 16;
                #pragma unroll
                for (int j = 0; j < 8; ++j) {
                    uint4 b = *(const uint4*)(bp0 + j * 512);
                    #pragma unroll
                    for (int mt = 0; mt < 2; ++mt) {
                        MMA_BF16(C[mt][j], ah[mt], b.x, b.y);
                        MMA_BF16(C[mt][j], ah[mt], b.z, b.w);
                        MMA_BF16(C[mt][j], al[mt], b.x, b.y);
                    }
                }
            }
        }
    };

    // ---- layer-1 pre-mix: X_mixed = A1 @ x from gmem, split hi/lo ----
    auto premix_x = [&](int kc) {
        __syncthreads();
        #pragma unroll 1
        for (int idx = tid; idx < 4096; idx += 256) {
            int r = idx >> 5, q = idx & 31;
            float4 s = make_float4(0.f, 0.f, 0.f, 0.f);
            if (r < rows_valid) {
                int n = rown[r];
                const int gbr = b0row + r - n;
                const int base = n * ANN, cnt = Acnt[n];
                for (int e = 0; e < cnt; ++e) {
                    float a = Aw[base + e];
                    const float4 v = __ldg((const float4*)(x + (size_t)(gbr + Ai[base+e]) * 256 + kc*128) + q);
                    s.x = fmaf(a, v.x, s.x); s.y = fmaf(a, v.y, s.y);
                    s.z = fmaf(a, v.z, s.z); s.w = fmaf(a, v.w, s.w);
                }
            }
            float h0 = __bfloat162float(__float2bfloat16(s.x));
            float h1 = __bfloat162float(__float2bfloat16(s.y));
            float h2 = __bfloat162float(__float2bfloat16(s.z));
            float h3 = __bfloat162float(__float2bfloat16(s.w));
            *(uint2*)(XH + r*LDX + q*4) = make_uint2(pack_bf2(h0, h1), pack_bf2(h2, h3));
            *(uint2*)(XL + r*LDX + q*4) =
                make_uint2(pack_bf2(s.x - h0, s.y - h1), pack_bf2(s.z - h2, s.w - h3));
        }
        __syncthreads();
    };

    // ---- layers 1/2 epilogue: bias+relu -> split store, in-place next-A premix ----
    auto epi12 = [&](const float* __restrict__ bias, int Lnext) {
        __syncthreads();
        #pragma unroll
        for (int mt = 0; mt < 2; ++mt)
            #pragma unroll
            for (int j = 0; j < 8; ++j) {
                int c  = ng*64 + j*8 + (lane&3)*2;
                float2 bb = __ldg((const float2*)(bias + c));
                int r0 = m0base + mt*16 + (lane>>2);
                float v00 = fmaxf(C[mt][j][0] + bb.x, 0.f);
                float v01 = fmaxf(C[mt][j][1] + bb.y, 0.f);
                float v10 = fmaxf(C[mt][j][2] + bb.x, 0.f);
                float v11 = fmaxf(C[mt][j][3] + bb.y, 0.f);
                float h00 = __bfloat162float(__float2bfloat16(v00));
                float h01 = __bfloat162float(__float2bfloat16(v01));
                float h10 = __bfloat162float(__float2bfloat16(v10));
                float h11 = __bfloat162float(__float2bfloat16(v11));
                *(uint32_t*)(XH + r0*LDX + c)     = pack_bf2(h00, h01);
                *(uint32_t*)(XL + r0*LDX + c)     = pack_bf2(v00 - h00, v01 - h01);
                *(uint32_t*)(XH + (r0+8)*LDX + c) = pack_bf2(h10, h11);
                *(uint32_t*)(XL + (r0+8)*LDX + c) = pack_bf2(v10 - h10, v11 - h11);
            }
        __syncthreads();
        #pragma unroll 1
        for (int ch = 0; ch < 4; ++ch) {
            float mv[16];
            #pragma unroll
            for (int t = 0; t < 16; ++t) {
                int idx = tid + t*256;
                int r = idx >> 5, c = (idx & 31) + ch*32;
                float s = 0.f;
                if (r < rows_valid) {
                    int n = rown[r], gb0 = r - n;
                    int base = (Lnext*21 + n)*ANN, cnt = Acnt[Lnext*21 + n];
                    for (int e = 0; e < cnt; ++e) {
                        int off = (gb0 + Ai[base+e]) * LDX + c;
                        s = fmaf(Aw[base+e],
                                 __bfloat162float(XH[off]) + __bfloat162float(XL[off]), s);
                    }
                }
                mv[t] = s;
            }
            __syncthreads();
            #pragma unroll
            for (int t = 0; t < 16; ++t) {
                int idx = tid + t*256;
                int r = idx >> 5, c = (idx & 31) + ch*32;
                float hi = __bfloat162float(__float2bfloat16(mv[t]));
                XH[r*LDX + c] = __float2bfloat16(hi);
                XL[r*LDX + c] = __float2bfloat16(mv[t] - hi);
            }
            __syncthreads();
        }
    };

    // ================= Layer 1: K=256 (2 pre-mixed chunks) =================
    ZERO_C();
    premix_x(0);
    sweepK(PAIR_W1,           16);
    premix_x(1);
    sweepK(PAIR_W1 + 8 * 16,  16);
    epi12(b1, 1);

    // ================= Layer 2: K=128 =================
    ZERO_C();
    sweepK(PAIR_W2, 16);
    epi12(b2, 2);

    // ================= Layer 3: K=128, N=512 (4 n-chunks), register epi =====
    #pragma unroll 1
    for (int nc = 0; nc < 4; ++nc) {
        ZERO_C();
        sweepK(PAIR_W3 + nc * 16, 64);
        float facc[12];
        #pragma unroll
        for (int i = 0; i < 12; ++i) facc[i] = 0.f;
        #pragma unroll
        for (int mt = 0; mt < 2; ++mt)
            #pragma unroll
            for (int j = 0; j < 8; ++j) {
                int cg = nc*128 + ng*64 + j*8 + (lane&3)*2;
                float2 bb = __ldg((const float2*)(b3 + cg));
                int r0 = m0base + mt*16 + (lane>>2);
                bool ok0 = (r0     < rows_valid);
                bool ok1 = (r0 + 8 < rows_valid);
                float v00 = ok0 ? fmaxf(C[mt][j][0] + bb.x, 0.f) : 0.f;
                float v01 = ok0 ? fmaxf(C[mt][j][1] + bb.y, 0.f) : 0.f;
                float v10 = ok1 ? fmaxf(C[mt][j][2] + bb.x, 0.f) : 0.f;
                float v11 = ok1 ? fmaxf(C[mt][j][3] + bb.y, 0.f) : 0.f;
                if (ok0) *(float2*)(x3g + (size_t)(b0row + r0    )*512 + cg) = make_float2(v00, v01);
                if (ok1) *(float2*)(x3g + (size_t)(b0row + r0 + 8)*512 + cg) = make_float2(v10, v11);
                #pragma unroll
                for (int jo = 0; jo < 3; ++jo) {
                    float w0 = __ldg(fcW + (size_t)cg*3 + jo);
                    float w1 = __ldg(fcW + (size_t)(cg+1)*3 + jo);
                    facc[(mt*2+0)*3 + jo] += v00*w0 + v01*w1;
                    facc[(mt*2+1)*3 + jo] += v10*w0 + v11*w1;
                }
            }
        #pragma unroll
        for (int i = 0; i < 12; ++i) {
            facc[i] += __shfl_xor_sync(0xFFFFFFFF, facc[i], 1);
            facc[i] += __shfl_xor_sync(0xFFFFFFFF, facc[i], 2);
        }
        if ((lane & 3) == 0) {
            #pragma unroll
            for (int mt = 0; mt < 2; ++mt)
                #pragma unroll
                for (int rh = 0; rh < 2; ++rh) {
                    int r = m0base + mt*16 + (lane>>2) + rh*8;
                    if (r < rows_valid) {
                        #pragma unroll
                        for (int jo = 0; jo < 3; ++jo)
                            atomicAdd(&Oac[r*3 + jo], facc[(mt*2+rh)*3 + jo]);
                    }
                }
        }
    }

    // ---- final out = FC + fcb ----
    __syncthreads();
    for (int w = tid; w < 378; w += 256) {
        int r = w / 3, j = w - 3*r;
        if (r < rows_valid)
            outg[(size_t)(b0row + r)*3 + j] = Oac[w] + __ldg(fcb + j);
    }
    #undef ZERO_C
}

extern "C" void kernel_launch(void* const* d_in, const int* in_sizes, int n_in,
                              void* d_out, int out_size) {
    const float* x   = (const float*)d_in[0];
    const float* A1  = (const float*)d_in[1];
    const float* A2  = (const float*)d_in[2];
    const float* A3  = (const float*)d_in[3];
    const float* W1  = (const float*)d_in[4];
    const float* b1  = (const float*)d_in[5];
    const float* W2  = (const float*)d_in[6];
    const float* b2  = (const float*)d_in[7];
    const float* W3  = (const float*)d_in[8];
    const float* b3  = (const float*)d_in[9];
    const float* fcW = (const float*)d_in[10];
    const float* fcb = (const float*)d_in[11];

    const int Btot = in_sizes[0] / (21 * 256);
    float* x3g  = (float*)d_out;
    float* outg = x3g + (size_t)Btot * 21 * 512;

    static int attr_done = 0;
    if (!attr_done) {
        cudaFuncSetAttribute(handnet_mma, cudaFuncAttributeMaxDynamicSharedMemorySize, SMEM_SZ);
        attr_done = 1;
    }

    prep_frags<<<NPAIR, 32>>>(W1, W2, W3);
    const int nCTA = (Btot * 21 + 125) / 126;
    handnet_mma<<<nCTA, 256, SMEM_SZ>>>(x, A1, A2, A3, b1, b2, b3, fcW, fcb,
                                        x3g, outg, Btot);
}

// round 9
// speedup vs baseline: 3.6596x; 1.4814x over previous
#include <cuda_runtime.h>
#include <cuda_fp16.h>
#include <cstdint>

// ============================================================
// Portable-PTX (base sm_103): ldmatrix + mma.sync fp16 (2-pass A-split)
// 3 CTAs/SM, M=64 rows per CTA, cp.async B pipeline (4-kstep units)
// ============================================================
__device__ __forceinline__ uint32_t smem_u32(const void* p) {
    uint32_t a;
    asm("{ .reg .u64 t; cvta.to.shared.u64 t, %1; cvt.u32.u64 %0, t; }" : "=r"(a) : "l"(p));
    return a;
}
#define LDSM_X4(a0,a1,a2,a3,addr) \
    asm volatile("ldmatrix.sync.aligned.m8n8.x4.shared.b16 {%0,%1,%2,%3}, [%4];" \
        : "=r"(a0), "=r"(a1), "=r"(a2), "=r"(a3) : "r"(addr))
#define MMA_F16(c, a, b0, b1) \
    asm volatile("mma.sync.aligned.m16n8k16.row.col.f32.f16.f16.f32 " \
        "{%0,%1,%2,%3}, {%4,%5,%6,%7}, {%8,%9}, {%0,%1,%2,%3};" \
        : "+f"((c)[0]), "+f"((c)[1]), "+f"((c)[2]), "+f"((c)[3]) \
        : "r"((a)[0]), "r"((a)[1]), "r"((a)[2]), "r"((a)[3]), "r"(b0), "r"(b1))
__device__ __forceinline__ void cp16(uint32_t dst, const void* src) {
    asm volatile("cp.async.ca.shared.global [%0], [%1], 16;" :: "r"(dst), "l"(src));
}
#define CP_COMMIT()  asm volatile("cp.async.commit_group;" ::: "memory")
#define CP_WAIT(n)   asm volatile("cp.async.wait_group %0;" :: "n"(n) : "memory")

namespace {
constexpr int LDX  = 136;   // fp16 row stride (272 B = 17*16B -> LDSM conflict-free)
constexpr int ANN  = 12;    // max nnz per A row
constexpr int MROW = 64;    // rows per CTA tile (63 valid = 3 batches)
constexpr int RPC  = 63;
// dynamic smem offsets
constexpr int OFF_XH   = 0;            // [64][136] fp16 = 17408
constexpr int OFF_XL   = 17408;        // [64][136] fp16 = 17408
constexpr int OFF_B    = 34816;        // 2 slots x 16384 = 32768
constexpr int OFF_AW   = 67584;        // [3][21][12] f32 = 3024
constexpr int OFF_AI   = 70608;        // [3][21][12] u8  = 768
constexpr int OFF_ACNT = 71376;        // i32[64]  = 256
constexpr int OFF_OAC  = 71632;        // f32[192] = 768
constexpr int OFF_ROWN = 72400;        // u8[64]
constexpr int SMEM_SZ  = 72576;        // x3 CTAs = 213 KB < 227 KB
// fragment bases (1 frag = B-hi for one (kstep, n-tile); 256 B = 32 lanes x 8 B)
constexpr int FR_W1 = 0;      // 16 ks * 16 nt = 256
constexpr int FR_W2 = 256;    //  8 ks * 16 nt = 128
constexpr int FR_W3 = 384;    //  8 ks * 64 nt = 512
constexpr int NFRAG = 896;
} // namespace

// Per-lane B-hi fragments (fp16x2 pairs). 16 consecutive frags (one CTA k-step)
// = 4 KB contiguous -> bulk cp.async. L2-resident (229 KB).
__device__ __align__(16) uint2 gWB[NFRAG][32];

__device__ __forceinline__ uint32_t pack_h2(float x, float y) {
    __half2 h = __floats2half2_rn(x, y);
    return *reinterpret_cast<uint32_t*>(&h);
}

// frag id = base + ks*NT + nt
__global__ void prep_frags(const float* __restrict__ W1,
                           const float* __restrict__ W2,
                           const float* __restrict__ W3) {
    const int id = blockIdx.x, l = threadIdx.x;
    const float* W; int ld, r, NT;
    if (id < 256)      { W = W1; ld = 128; r = id;       NT = 16; }
    else if (id < 384) { W = W2; ld = 128; r = id - 256; NT = 16; }
    else               { W = W3; ld = 512; r = id - 384; NT = 64; }
    const int nt = r % NT, ks = r / NT;
    const int n  = nt * 8 + (l >> 2);
    const int k0 = ks * 16 + (l & 3) * 2;
    float v[4];
    #pragma unroll
    for (int i = 0; i < 4; ++i)
        v[i] = W[(size_t)(k0 + (i >> 1) * 8 + (i & 1)) * ld + n];
    gWB[id][l] = make_uint2(pack_h2(v[0], v[1]), pack_h2(v[2], v[3]));
}

__global__ void __launch_bounds__(256, 3)
handnet_mma(const float* __restrict__ x,
            const float* __restrict__ A1, const float* __restrict__ A2,
            const float* __restrict__ A3,
            const float* __restrict__ b1, const float* __restrict__ b2,
            const float* __restrict__ b3,
            const float* __restrict__ fcW, const float* __restrict__ fcb,
            float* __restrict__ x3g, float* __restrict__ outg, int Btot)
{
    extern __shared__ unsigned char sm[];
    __half*  XH   = (__half*)(sm + OFF_XH);
    __half*  XL   = (__half*)(sm + OFF_XL);
    float*   Aw   = (float*)(sm + OFF_AW);
    uint8_t* Ai   = sm + OFF_AI;
    int*     Acnt = (int*)(sm + OFF_ACNT);
    float*   Oac  = (float*)(sm + OFF_OAC);
    uint8_t* rown = sm + OFF_ROWN;

    const int tid = threadIdx.x, lane = tid & 31, wid = tid >> 5;
    const int mg = wid >> 2, ng = wid & 3;        // 2 m-groups x 4 n-groups
    const int m0base = mg * 32;
    const int arow = m0base + (lane & 7) + ((lane >> 3) & 1) * 8;
    const int kadd = ((lane >> 4) & 1) * 8;
    const uint32_t xh = smem_u32(XH), xl = smem_u32(XL);
    const uint32_t smB = smem_u32(sm + OFF_B);

    const int b0row = blockIdx.x * RPC;
    const int rows_valid = min(RPC, Btot * 21 - b0row);

    // ---- setup ----
    if (tid < MROW) rown[tid] = (uint8_t)(tid % 21);
    if (tid < 63) {
        int L = tid / 21, n = tid % 21;
        const float* A = (L == 0) ? A1 : ((L == 1) ? A2 : A3);
        int c = 0;
        for (int m = 0; m < 21 && c < ANN; ++m) {
            float v = __ldg(A + n * 21 + m);
            if (v != 0.f) { Aw[(L*21+n)*ANN + c] = v; Ai[(L*21+n)*ANN + c] = (uint8_t)m; ++c; }
        }
        Acnt[L * 21 + n] = c;
    }
    if (tid < 192) Oac[tid] = 0.f;
    __syncthreads();

    float C[2][4][4];
    #define ZERO_C() { _Pragma("unroll") for (int mt=0;mt<2;++mt) _Pragma("unroll") \
        for (int j=0;j<4;++j) { C[mt][j][0]=0.f;C[mt][j][1]=0.f;C[mt][j][2]=0.f;C[mt][j][3]=0.f; } }

    // cooperative load of one 4-kstep unit (4 x 4 KB) into a slot
    auto ldBunit = [&](int fb, int fstride, int slot) {
        #pragma unroll
        for (int h = 0; h < 4; ++h) {
            const char* src = (const char*)&gWB[fb + h * fstride][0] + tid * 16;
            cp16(smB + (uint32_t)slot * 16384u + (uint32_t)h * 4096u + (uint32_t)tid * 16u, src);
        }
        CP_COMMIT();
    };

    // ---- pipelined sweep: 8 ksteps = 2 units of 4; 1 barrier per unit ----
    auto sweepK = [&](int fragbase, int fstride) {
        __syncthreads();                           // prev readers of slot0 done
        ldBunit(fragbase, fstride, 0);
        #pragma unroll 1
        for (int u = 0; u < 2; ++u) {
            CP_WAIT(0);
            __syncthreads();
            if (u == 0) ldBunit(fragbase + 4 * fstride, fstride, 1);
            #pragma unroll
            for (int k4 = 0; k4 < 4; ++k4) {
                const int ks = u * 4 + k4;
                uint32_t ah[2][4], al[2][4];
                #pragma unroll
                for (int mt = 0; mt < 2; ++mt) {
                    uint32_t off = (uint32_t)(((arow + mt*16) * LDX + ks*16 + kadd) * 2);
                    LDSM_X4(ah[mt][0], ah[mt][1], ah[mt][2], ah[mt][3], xh + off);
                    LDSM_X4(al[mt][0], al[mt][1], al[mt][2], al[mt][3], xl + off);
                }
                const unsigned char* bp0 = sm + OFF_B + (u & 1) * 16384 + k4 * 4096
                                             + ng * 4 * 256 + lane * 8;
                #pragma unroll
                for (int j = 0; j < 4; ++j) {
                    uint2 b = *(const uint2*)(bp0 + j * 256);
                    #pragma unroll
                    for (int mt = 0; mt < 2; ++mt) {
                        MMA_F16(C[mt][j], ah[mt], b.x, b.y);
                        MMA_F16(C[mt][j], al[mt], b.x, b.y);
                    }
                }
            }
        }
    };

    // ---- layer-1 pre-mix: X_mixed = A1 @ x gathered from gmem, fp16 split ----
    auto premix_x = [&](int kc) {
        __syncthreads();
        #pragma unroll 1
        for (int idx = tid; idx < MROW * 32; idx += 256) {
            int r = idx >> 5, q = idx & 31;
            float4 s = make_float4(0.f, 0.f, 0.f, 0.f);
            if (r < rows_valid) {
                int n = rown[r];
                const int gbr = b0row + r - n;
                const int base = n * ANN, cnt = Acnt[n];
                for (int e = 0; e < cnt; ++e) {
                    float a = Aw[base + e];
                    const float4 v = __ldg((const float4*)(x + (size_t)(gbr + Ai[base+e]) * 256 + kc*128) + q);
                    s.x = fmaf(a, v.x, s.x); s.y = fmaf(a, v.y, s.y);
                    s.z = fmaf(a, v.z, s.z); s.w = fmaf(a, v.w, s.w);
                }
            }
            float h0 = __half2float(__float2half_rn(s.x));
            float h1 = __half2float(__float2half_rn(s.y));
            float h2 = __half2float(__float2half_rn(s.z));
            float h3 = __half2float(__float2half_rn(s.w));
            *(uint2*)(XH + r*LDX + q*4) = make_uint2(pack_h2(h0, h1), pack_h2(h2, h3));
            *(uint2*)(XL + r*LDX + q*4) =
                make_uint2(pack_h2(s.x - h0, s.y - h1), pack_h2(s.z - h2, s.w - h3));
        }
        __syncthreads();
    };

    // ---- layers 1/2 epilogue: bias+relu -> split store, in-place next-A premix ----
    auto epi12 = [&](const float* __restrict__ bias, int Lnext) {
        __syncthreads();
        #pragma unroll
        for (int mt = 0; mt < 2; ++mt)
            #pragma unroll
            for (int j = 0; j < 4; ++j) {
                int c  = ng*32 + j*8 + (lane&3)*2;
                float2 bb = __ldg((const float2*)(bias + c));
                int r0 = m0base + mt*16 + (lane>>2);
                float v00 = fmaxf(C[mt][j][0] + bb.x, 0.f);
                float v01 = fmaxf(C[mt][j][1] + bb.y, 0.f);
                float v10 = fmaxf(C[mt][j][2] + bb.x, 0.f);
                float v11 = fmaxf(C[mt][j][3] + bb.y, 0.f);
                float h00 = __half2float(__float2half_rn(v00));
                float h01 = __half2float(__float2half_rn(v01));
                float h10 = __half2float(__float2half_rn(v10));
                float h11 = __half2float(__float2half_rn(v11));
                *(uint32_t*)(XH + r0*LDX + c)     = pack_h2(h00, h01);
                *(uint32_t*)(XL + r0*LDX + c)     = pack_h2(v00 - h00, v01 - h01);
                *(uint32_t*)(XH + (r0+8)*LDX + c) = pack_h2(h10, h11);
                *(uint32_t*)(XL + (r0+8)*LDX + c) = pack_h2(v10 - h10, v11 - h11);
            }
        __syncthreads();
        #pragma unroll 1
        for (int ch = 0; ch < 4; ++ch) {
            float mv[8];
            #pragma unroll
            for (int t = 0; t < 8; ++t) {
                int idx = tid + t*256;
                int r = idx >> 5, c = (idx & 31) + ch*32;
                float s = 0.f;
                if (r < rows_valid) {
                    int n = rown[r], gb0 = r - n;
                    int base = (Lnext*21 + n)*ANN, cnt = Acnt[Lnext*21 + n];
                    for (int e = 0; e < cnt; ++e) {
                        int off = (gb0 + Ai[base+e]) * LDX + c;
                        s = fmaf(Aw[base+e],
                                 __half2float(XH[off]) + __half2float(XL[off]), s);
                    }
                }
                mv[t] = s;
            }
            __syncthreads();
            #pragma unroll
            for (int t = 0; t < 8; ++t) {
                int idx = tid + t*256;
                int r = idx >> 5, c = (idx & 31) + ch*32;
                float hi = __half2float(__float2half_rn(mv[t]));
                XH[r*LDX + c] = __float2half_rn(hi);
                XL[r*LDX + c] = __float2half_rn(mv[t] - hi);
            }
            __syncthreads();
        }
    };

    // ================= Layer 1: K=256 (2 pre-mixed chunks) =================
    ZERO_C();
    premix_x(0);
    sweepK(FR_W1,          16);
    premix_x(1);
    sweepK(FR_W1 + 8 * 16, 16);
    epi12(b1, 1);

    // ================= Layer 2: K=128 =================
    ZERO_C();
    sweepK(FR_W2, 16);
    epi12(b2, 2);

    // ================= Layer 3: K=128, N=512 (4 n-chunks), register epi =====
    #pragma unroll 1
    for (int nc = 0; nc < 4; ++nc) {
        ZERO_C();
        sweepK(FR_W3 + nc * 16, 64);
        float facc[12];
        #pragma unroll
        for (int i = 0; i < 12; ++i) facc[i] = 0.f;
        #pragma unroll
        for (int mt = 0; mt < 2; ++mt)
            #pragma unroll
            for (int j = 0; j < 4; ++j) {
                int cg = nc*128 + ng*32 + j*8 + (lane&3)*2;
                float2 bb = __ldg((const float2*)(b3 + cg));
                int r0 = m0base + mt*16 + (lane>>2);
                bool ok0 = (r0     < rows_valid);
                bool ok1 = (r0 + 8 < rows_valid);
                float v00 = ok0 ? fmaxf(C[mt][j][0] + bb.x, 0.f) : 0.f;
                float v01 = ok0 ? fmaxf(C[mt][j][1] + bb.y, 0.f) : 0.f;
                float v10 = ok1 ? fmaxf(C[mt][j][2] + bb.x, 0.f) : 0.f;
                float v11 = ok1 ? fmaxf(C[mt][j][3] + bb.y, 0.f) : 0.f;
                if (ok0) *(float2*)(x3g + (size_t)(b0row + r0    )*512 + cg) = make_float2(v00, v01);
                if (ok1) *(float2*)(x3g + (size_t)(b0row + r0 + 8)*512 + cg) = make_float2(v10, v11);
                #pragma unroll
                for (int jo = 0; jo < 3; ++jo) {
                    float w0 = __ldg(fcW + (size_t)cg*3 + jo);
                    float w1 = __ldg(fcW + (size_t)(cg+1)*3 + jo);
                    facc[(mt*2+0)*3 + jo] += v00*w0 + v01*w1;
                    facc[(mt*2+1)*3 + jo] += v10*w0 + v11*w1;
                }
            }
        #pragma unroll
        for (int i = 0; i < 12; ++i) {
            facc[i] += __shfl_xor_sync(0xFFFFFFFF, facc[i], 1);
            facc[i] += __shfl_xor_sync(0xFFFFFFFF, facc[i], 2);
        }
        if ((lane & 3) == 0) {
            #pragma unroll
            for (int mt = 0; mt < 2; ++mt)
                #pragma unroll
                for (int rh = 0; rh < 2; ++rh) {
                    int r = m0base + mt*16 + (lane>>2) + rh*8;
                    if (r < rows_valid) {
                        #pragma unroll
                        for (int jo = 0; jo < 3; ++jo)
                            atomicAdd(&Oac[r*3 + jo], facc[(mt*2+rh)*3 + jo]);
                    }
                }
        }
    }

    // ---- final out = FC + fcb ----
    __syncthreads();
    if (tid < 189) {
        int r = tid / 3, j = tid - 3*r;
        if (r < rows_valid)
            outg[(size_t)(b0row + r)*3 + j] = Oac[tid] + __ldg(fcb + j);
    }
    #undef ZERO_C
}

extern "C" void kernel_launch(void* const* d_in, const int* in_sizes, int n_in,
                              void* d_out, int out_size) {
    const float* x   = (const float*)d_in[0];
    const float* A1  = (const float*)d_in[1];
    const float* A2  = (const float*)d_in[2];
    const float* A3  = (const float*)d_in[3];
    const float* W1  = (const float*)d_in[4];
    const float* b1  = (const float*)d_in[5];
    const float* W2  = (const float*)d_in[6];
    const float* b2  = (const float*)d_in[7];
    const float* W3  = (const float*)d_in[8];
    const float* b3  = (const float*)d_in[9];
    const float* fcW = (const float*)d_in[10];
    const float* fcb = (const float*)d_in[11];

    const int Btot = in_sizes[0] / (21 * 256);
    float* x3g  = (float*)d_out;
    float* outg = x3g + (size_t)Btot * 21 * 512;

    static int attr_done = 0;
    if (!attr_done) {
        cudaFuncSetAttribute(handnet_mma, cudaFuncAttributeMaxDynamicSharedMemorySize, SMEM_SZ);
        attr_done = 1;
    }

    prep_frags<<<NFRAG, 32>>>(W1, W2, W3);
    const int nCTA = (Btot * 21 + RPC - 1) / RPC;
    handnet_mma<<<nCTA, 256, SMEM_SZ>>>(x, A1, A2, A3, b1, b2, b3, fcW, fcb,
                                        x3g, outg, Btot);
}